// round 15
// baseline (speedup 1.0000x reference)
#include <cuda_runtime.h>
#include <math.h>

#define BB 16
#define HH 512
#define WW 512
#define NTOT (BB * HH * WW)

#define RAD 10
#define STRIP 16                   // output rows per block
#define HROWS (STRIP + 2 * RAD)    // 36 halo rows
#define NSTRIP (HH / STRIP)        // 32
#define NB (NSTRIP * BB)           // 512 blocks
#define SENTW 0x64646464u          // four u8 bytes of 100

__device__ float g_pl[NB];
__device__ float g_pf[NB];
__device__ unsigned g_done = 0;  // last-block counter (self-resetting)

// ---------------------------------------------------------------------------
// Single fused kernel. Block = 16x512 output strip of one batch image.
// Phase A: build f^2-u8 (horizontal pass, K1's shfl/clz scheme) for the 36
//   halo rows directly from tgt into SMEM (no global scratch). Halo re-reads
//   (2.25x) are L2-served since neighbor strips run concurrently; unique tgt
//   DRAM traffic stays 16.7 MB. Per-row activity flag via warp ballot.
// Phase B: per-warp (2 output rows x 512 cols): activity ballot over the
//   22-row window, sparse SIMD-u8 min-plus taps (vminu4/vaddus4, ~2 active
//   rows avg); branch-free select epilogue on the inp stream:
//   pos=(d==0) exact (<=> fg px); h=exp(-d/8); a=pos?0.85:0.15; s=pos?q:p;
//   e=pos?q:(p-h); focal=a*s^2; loss=focal*e^2.
// Shuffle reduce -> per-block partials; last block folds the final scalar.
// d=100 sentinel where no fg within dist 10 -> h=exp(-12.5)=3.7e-6 vs true
// heatmap <= exp(-100/8) — loss-equivalent far inside the 1e-3 budget.
// ---------------------------------------------------------------------------
__global__ __launch_bounds__(256) void k_fused(const float* __restrict__ inp,
                                               const float* __restrict__ tgt,
                                               float* __restrict__ out) {
    const int tid = threadIdx.x;
    const int lane = tid & 31;
    const int wid = tid >> 5;          // 8 warps
    const int strip = blockIdx.x;      // 0..31
    const int b = blockIdx.y;          // 0..15
    const int i0 = strip * STRIP;

    __shared__ __align__(16) unsigned sf2[HROWS][WW / 4];  // 18.4 KB u8-packed f^2
    __shared__ unsigned char srowact[HROWS];
    __shared__ float swF[8];
    __shared__ float swL[8];
    __shared__ int slast;

    // ---------------- Phase A: horizontal pass into SMEM ----------------
    for (int rr = wid; rr < HROWS; rr += 8) {
        int gr = i0 - RAD + rr;
        unsigned ow0 = SENTW, ow1 = SENTW, ow2 = SENTW, ow3 = SENTW;
        bool actl = false;
        if ((unsigned)gr < HH) {
            const float4* p =
                (const float4*)(tgt + ((size_t)(b * HH + gr)) * WW + lane * 16);
            float4 v0 = p[0], v1 = p[1], v2 = p[2], v3 = p[3];
            unsigned m = 0;
            m |= (v0.x > 0.5f) ? 1u << 0 : 0u;
            m |= (v0.y > 0.5f) ? 1u << 1 : 0u;
            m |= (v0.z > 0.5f) ? 1u << 2 : 0u;
            m |= (v0.w > 0.5f) ? 1u << 3 : 0u;
            m |= (v1.x > 0.5f) ? 1u << 4 : 0u;
            m |= (v1.y > 0.5f) ? 1u << 5 : 0u;
            m |= (v1.z > 0.5f) ? 1u << 6 : 0u;
            m |= (v1.w > 0.5f) ? 1u << 7 : 0u;
            m |= (v2.x > 0.5f) ? 1u << 8 : 0u;
            m |= (v2.y > 0.5f) ? 1u << 9 : 0u;
            m |= (v2.z > 0.5f) ? 1u << 10 : 0u;
            m |= (v2.w > 0.5f) ? 1u << 11 : 0u;
            m |= (v3.x > 0.5f) ? 1u << 12 : 0u;
            m |= (v3.y > 0.5f) ? 1u << 13 : 0u;
            m |= (v3.z > 0.5f) ? 1u << 14 : 0u;
            m |= (v3.w > 0.5f) ? 1u << 15 : 0u;

            unsigned left = __shfl_up_sync(0xffffffffu, m, 1);
            unsigned right = __shfl_down_sync(0xffffffffu, m, 1);
            if (lane == 0) left = 0;
            if (lane == 31) right = 0;
            unsigned long long w = (unsigned long long)left |
                                   ((unsigned long long)m << 16) |
                                   ((unsigned long long)right << 32);
            unsigned owl[4];
#pragma unroll
            for (int k = 0; k < 4; k++) {
                unsigned bw = 0;
#pragma unroll
                for (int u = 0; u < 4; u++) {
                    int pcol = 4 * k + u;
                    unsigned win = (unsigned)(w >> (pcol + 6)) & 0x1FFFFFu;
                    unsigned wl = win & 0x7FFu;
                    int dl = __clz(wl) - 21;             // 0..11
                    unsigned wr = (win >> 10) | 0x800u;
                    int dr = __ffs((int)wr) - 1;         // 0..11
                    int f = min(min(dl, dr), 10);
                    bw |= (unsigned)(f * f) << (8 * u);
                }
                owl[k] = bw;
            }
            ow0 = owl[0]; ow1 = owl[1]; ow2 = owl[2]; ow3 = owl[3];
            actl = ((ow0 ^ SENTW) | (ow1 ^ SENTW) | (ow2 ^ SENTW) |
                    (ow3 ^ SENTW)) != 0u;
        }
        *(uint4*)&sf2[rr][lane * 4] = make_uint4(ow0, ow1, ow2, ow3);
        unsigned blt = __ballot_sync(0xffffffffu, actl);
        if (lane == 0) srowact[rr] = (blt != 0u) ? 1 : 0;
    }
    __syncthreads();

    // ---------------- Phase B: vertical taps + loss ----------------
    // warp wid owns output rows 2*wid, 2*wid+1 (halo rows 2*wid+10, +11).
    const int hr0 = 2 * wid + RAD;  // halo index of first output row

    bool act = (lane < 22) ? (srowact[2 * wid + lane] != 0) : false;
    unsigned rm = __ballot_sync(0xffffffffu, act) & 0x3FFFFFu;

    uint4 a0 = make_uint4(SENTW, SENTW, SENTW, SENTW);
    uint4 a1 = a0;
    while (rm) {
        int t = __ffs(rm) - 1;   // tap at halo row 2*wid + t
        rm &= rm - 1;
        uint4 v = *(const uint4*)&sf2[2 * wid + t][lane * 4];
        int dm0 = (2 * wid + t) - hr0;
        int w0 = min(dm0 * dm0, 100);
        int dm1 = dm0 - 1;
        int w1 = min(dm1 * dm1, 100);
        unsigned w0b = (unsigned)w0 * 0x01010101u;
        unsigned w1b = (unsigned)w1 * 0x01010101u;
        a0.x = __vminu4(a0.x, __vaddus4(v.x, w0b));
        a0.y = __vminu4(a0.y, __vaddus4(v.y, w0b));
        a0.z = __vminu4(a0.z, __vaddus4(v.z, w0b));
        a0.w = __vminu4(a0.w, __vaddus4(v.w, w0b));
        a1.x = __vminu4(a1.x, __vaddus4(v.x, w1b));
        a1.y = __vminu4(a1.y, __vaddus4(v.y, w1b));
        a1.z = __vminu4(a1.z, __vaddus4(v.z, w1b));
        a1.w = __vminu4(a1.w, __vaddus4(v.w, w1b));
    }

    float fsum = 0.0f, lsum = 0.0f;
#define PXE(accw, k, xv)                                      \
    {                                                         \
        int d = ((accw) >> (8 * (k))) & 255;                  \
        float h = __expf((float)d * -0.125f);                 \
        bool pos = (d == 0);                                  \
        float p = __fdividef(1.0f, 1.0f + __expf(-(xv)));     \
        float qq = 1.0f - p;                                  \
        float a = pos ? 0.85f : 0.15f;                        \
        float ss = pos ? qq : p;                              \
        float e = pos ? qq : (p - h);                         \
        float f = a * ss * ss;                                \
        fsum += f;                                            \
        lsum = fmaf(f * e, e, lsum);                          \
    }
    // row 0: 4 front-batched LDG.128 (MLP=4), 16 px
    {
        const float4* xp =
            (const float4*)(inp + ((size_t)(b * HH + i0 + 2 * wid)) * WW + lane * 16);
        float4 x0 = xp[0], x1 = xp[1], x2 = xp[2], x3 = xp[3];
        PXE(a0.x, 0, x0.x) PXE(a0.x, 1, x0.y) PXE(a0.x, 2, x0.z) PXE(a0.x, 3, x0.w)
        PXE(a0.y, 0, x1.x) PXE(a0.y, 1, x1.y) PXE(a0.y, 2, x1.z) PXE(a0.y, 3, x1.w)
        PXE(a0.z, 0, x2.x) PXE(a0.z, 1, x2.y) PXE(a0.z, 2, x2.z) PXE(a0.z, 3, x2.w)
        PXE(a0.w, 0, x3.x) PXE(a0.w, 1, x3.y) PXE(a0.w, 2, x3.z) PXE(a0.w, 3, x3.w)
    }
    // row 1
    {
        const float4* xp =
            (const float4*)(inp + ((size_t)(b * HH + i0 + 2 * wid + 1)) * WW + lane * 16);
        float4 x0 = xp[0], x1 = xp[1], x2 = xp[2], x3 = xp[3];
        PXE(a1.x, 0, x0.x) PXE(a1.x, 1, x0.y) PXE(a1.x, 2, x0.z) PXE(a1.x, 3, x0.w)
        PXE(a1.y, 0, x1.x) PXE(a1.y, 1, x1.y) PXE(a1.y, 2, x1.z) PXE(a1.y, 3, x1.w)
        PXE(a1.z, 0, x2.x) PXE(a1.z, 1, x2.y) PXE(a1.z, 2, x2.z) PXE(a1.z, 3, x2.w)
        PXE(a1.w, 0, x3.x) PXE(a1.w, 1, x3.y) PXE(a1.w, 2, x3.z) PXE(a1.w, 3, x3.w)
    }
#undef PXE

    // ---------------- reduce + last-block finalize ----------------
    float thF = fsum, thL = lsum;
#pragma unroll
    for (int off = 16; off > 0; off >>= 1) {
        thF += __shfl_xor_sync(0xffffffffu, thF, off);
        thL += __shfl_xor_sync(0xffffffffu, thL, off);
    }
    if (lane == 0) {
        swF[wid] = thF;
        swL[wid] = thL;
    }
    __syncthreads();

    const int bid = blockIdx.x + NSTRIP * blockIdx.y;
    if (tid == 0) {
        float F = 0.0f, Lv = 0.0f;
#pragma unroll
        for (int w = 0; w < 8; w++) {
            F += swF[w];
            Lv += swL[w];
        }
        g_pf[bid] = F;
        g_pl[bid] = Lv;
        __threadfence();
        unsigned old = atomicAdd(&g_done, 1u);
        slast = (old == NB - 1) ? 1 : 0;
    }
    __syncthreads();

    if (slast) {
        __threadfence();
        double* sFd = (double*)&sf2[0][0];  // reuse smem
        double* sLd = sFd + 256;
        double f = 0.0, l = 0.0;
        for (int i = tid; i < NB; i += 256) {
            f += (double)g_pf[i];
            l += (double)g_pl[i];
        }
        sFd[tid] = f;
        sLd[tid] = l;
        __syncthreads();
#pragma unroll
        for (int s = 128; s > 0; s >>= 1) {
            if (tid < s) {
                sFd[tid] += sFd[tid + s];
                sLd[tid] += sLd[tid + s];
            }
            __syncthreads();
        }
        if (tid == 0) {
            double n = (double)NTOT;
            double denom = sFd[0] / n + 0.01;
            out[0] = (float)(2.0 * (sLd[0] / n) / denom);
            g_done = 0;  // reset for next graph replay
        }
    }
}

extern "C" void kernel_launch(void* const* d_in, const int* in_sizes, int n_in,
                              void* d_out, int out_size) {
    const float* inp = (const float*)d_in[0];
    const float* tgt = (const float*)d_in[1];
    float* out = (float*)d_out;

    dim3 g(NSTRIP, BB);
    k_fused<<<g, 256>>>(inp, tgt, out);
}

// round 16
// speedup vs baseline: 1.0146x; 1.0146x over previous
#include <cuda_runtime.h>
#include <math.h>

#define BB 16
#define HH 512
#define WW 512
#define NTOT (BB * HH * WW)

#define RAD 10
#define NROWS (BB * HH)   // 8192
#define NB 1024           // K2 blocks (8 rows each)
#define SENTW 0x64646464u // four u8 bytes of 100

// Scratch (no allocation allowed in kernel_launch)
__device__ unsigned char g_f2[NTOT];    // horizontal distance^2 (<=100), u8
__device__ unsigned char g_acb[NROWS];  // per-row activity (any fg in row)
__device__ float g_pl[NB];
__device__ float g_pf[NB];
__device__ unsigned g_done = 0;  // last-block counter (self-resetting)

// ---------------------------------------------------------------------------
// K1: one WARP per image row, streaming tgt once. Each lane: 16 cols ->
// 16-bit fg mask; neighbor masks via 2 shfls; per-col horizontal distance f
// (clamped to 10: d>=10 -> heatmap <= exp(-100/8)=3.7e-6 ~ 0, loss-equiv)
// via clz/ffs on a 21-bit window. Stores f^2 as u8 + one activity byte per
// row (row has any fg). Bit math rides the tgt stream (12% issue when bare).
// ---------------------------------------------------------------------------
__global__ __launch_bounds__(256) void k1_f2(const float* __restrict__ tgt) {
    const int gid = blockIdx.x * 256 + threadIdx.x;
    const int row = gid >> 5;
    const int lane = gid & 31;
    const float4* p = (const float4*)(tgt + (size_t)row * WW + lane * 16);
    float4 v0 = p[0], v1 = p[1], v2 = p[2], v3 = p[3];

    unsigned m = 0;
    m |= (v0.x > 0.5f) ? 1u << 0 : 0u;
    m |= (v0.y > 0.5f) ? 1u << 1 : 0u;
    m |= (v0.z > 0.5f) ? 1u << 2 : 0u;
    m |= (v0.w > 0.5f) ? 1u << 3 : 0u;
    m |= (v1.x > 0.5f) ? 1u << 4 : 0u;
    m |= (v1.y > 0.5f) ? 1u << 5 : 0u;
    m |= (v1.z > 0.5f) ? 1u << 6 : 0u;
    m |= (v1.w > 0.5f) ? 1u << 7 : 0u;
    m |= (v2.x > 0.5f) ? 1u << 8 : 0u;
    m |= (v2.y > 0.5f) ? 1u << 9 : 0u;
    m |= (v2.z > 0.5f) ? 1u << 10 : 0u;
    m |= (v2.w > 0.5f) ? 1u << 11 : 0u;
    m |= (v3.x > 0.5f) ? 1u << 12 : 0u;
    m |= (v3.y > 0.5f) ? 1u << 13 : 0u;
    m |= (v3.z > 0.5f) ? 1u << 14 : 0u;
    m |= (v3.w > 0.5f) ? 1u << 15 : 0u;

    unsigned anyb = __ballot_sync(0xffffffffu, m != 0u);

    unsigned left = __shfl_up_sync(0xffffffffu, m, 1);
    unsigned right = __shfl_down_sync(0xffffffffu, m, 1);
    if (lane == 0) left = 0;
    if (lane == 31) right = 0;
    unsigned long long w = (unsigned long long)left |
                           ((unsigned long long)m << 16) |
                           ((unsigned long long)right << 32);

    unsigned ow[4];
#pragma unroll
    for (int k = 0; k < 4; k++) {
        unsigned bw = 0;
#pragma unroll
        for (int u = 0; u < 4; u++) {
            int pcol = 4 * k + u;
            unsigned win = (unsigned)(w >> (pcol + 6)) & 0x1FFFFFu;  // p-10..p+10
            unsigned wl = win & 0x7FFu;          // p-10..p (bit10 = center)
            int dl = __clz(wl) - 21;             // 0..11
            unsigned wr = (win >> 10) | 0x800u;  // p..p+10 + sentinel
            int dr = __ffs((int)wr) - 1;         // 0..11
            int f = min(min(dl, dr), 10);
            bw |= (unsigned)(f * f) << (8 * u);
        }
        ow[k] = bw;
    }
    *(uint4*)(g_f2 + (size_t)row * WW + lane * 16) =
        make_uint4(ow[0], ow[1], ow[2], ow[3]);
    if (lane == 0) g_acb[row] = (anyb != 0u) ? 1 : 0;
}

// ---------------------------------------------------------------------------
// K2: one WARP per image row — K1's proven shape. NO smem tile, NO barriers,
// NO atomics in the hot path. Lane owns 16 consecutive px.
//  0) 4 front-batched inp LDG.128 (independent -> latency hidden under taps)
//  1) activity: lanes 0..20 load one byte for rows i-10..i+10 (1 sector),
//     one ballot -> 21-bit tap mask (out-of-image rows -> 0)
//  2) sparse taps (~8 avg): LDG.128 of f^2 u8 from L2-resident g_f2, SIMD
//     min-plus vminu4(vaddus4(v, (t-10)^2 * 0x01010101)); acc init 100
//  3) branch-free select epilogue: pos=(d==0) exact (<=> fg px);
//     h=exp(-d/8); a=pos?0.85:0.15; s=pos?q:p; e=pos?q:(p-h);
//     focal=a*s^2; loss=focal*e^2
//  4) shuffle reduce + tiny block fold; last block computes the scalar.
// d=100 sentinel -> h=exp(-12.5)=3.7e-6 vs true heatmap <= exp(-100/8):
// loss-equivalent far inside the 1e-3 budget (validated rel_err ~8e-6).
// ---------------------------------------------------------------------------
__global__ __launch_bounds__(256) void k2_main(const float* __restrict__ inp,
                                               float* __restrict__ out) {
    const int tid = threadIdx.x;
    const int lane = tid & 31;
    const int wid = tid >> 5;
    const int gr = blockIdx.x * 8 + wid;  // global row 0..8191
    const int b = gr >> 9;
    const int i = gr & 511;

    __shared__ float swF[8];
    __shared__ float swL[8];
    __shared__ int slast;
    __shared__ double sred[512];

    // --- 0) front-batched inp loads (independent of everything below) ---
    const float4* xp = (const float4*)(inp + (size_t)gr * WW + lane * 16);
    float4 x0 = xp[0], x1 = xp[1], x2 = xp[2], x3 = xp[3];

    // --- 1) activity ballot over rows i-10..i+10 ---
    int r = i - RAD + lane;
    unsigned char ab = 0;
    if (lane < 2 * RAD + 1 && (unsigned)r < HH) ab = g_acb[(b << 9) + r];
    unsigned rm = __ballot_sync(0xffffffffu, ab != 0) & 0x1FFFFFu;

    // --- 2) sparse SIMD-u8 taps straight from L2 ---
    uint4 acc = make_uint4(SENTW, SENTW, SENTW, SENTW);
    const unsigned char* fb =
        g_f2 + ((size_t)(b << 9) + (i - RAD)) * WW + lane * 16;
    while (rm) {
        int t = __ffs(rm) - 1;
        rm &= rm - 1;
        uint4 v = *(const uint4*)(fb + (size_t)t * WW);
        int dm = t - RAD;
        unsigned wb = (unsigned)(dm * dm) * 0x01010101u;
        acc.x = __vminu4(acc.x, __vaddus4(v.x, wb));
        acc.y = __vminu4(acc.y, __vaddus4(v.y, wb));
        acc.z = __vminu4(acc.z, __vaddus4(v.z, wb));
        acc.w = __vminu4(acc.w, __vaddus4(v.w, wb));
    }

    // --- 3) branch-free select epilogue (16 px) ---
    float fsum = 0.0f, lsum = 0.0f;
#define PXE(accw, k, xv)                                      \
    {                                                         \
        int d = ((accw) >> (8 * (k))) & 255;                  \
        float h = __expf((float)d * -0.125f);                 \
        bool pos = (d == 0);                                  \
        float p = __fdividef(1.0f, 1.0f + __expf(-(xv)));     \
        float qq = 1.0f - p;                                  \
        float a = pos ? 0.85f : 0.15f;                        \
        float ss = pos ? qq : p;                              \
        float e = pos ? qq : (p - h);                         \
        float f = a * ss * ss;                                \
        fsum += f;                                            \
        lsum = fmaf(f * e, e, lsum);                          \
    }
    PXE(acc.x, 0, x0.x) PXE(acc.x, 1, x0.y) PXE(acc.x, 2, x0.z) PXE(acc.x, 3, x0.w)
    PXE(acc.y, 0, x1.x) PXE(acc.y, 1, x1.y) PXE(acc.y, 2, x1.z) PXE(acc.y, 3, x1.w)
    PXE(acc.z, 0, x2.x) PXE(acc.z, 1, x2.y) PXE(acc.z, 2, x2.z) PXE(acc.z, 3, x2.w)
    PXE(acc.w, 0, x3.x) PXE(acc.w, 1, x3.y) PXE(acc.w, 2, x3.z) PXE(acc.w, 3, x3.w)
#undef PXE

    // --- 4) reduce: warp shuffle, then tiny block fold ---
    float thF = fsum, thL = lsum;
#pragma unroll
    for (int off = 16; off > 0; off >>= 1) {
        thF += __shfl_xor_sync(0xffffffffu, thF, off);
        thL += __shfl_xor_sync(0xffffffffu, thL, off);
    }
    if (lane == 0) {
        swF[wid] = thF;
        swL[wid] = thL;
    }
    __syncthreads();

    if (tid == 0) {
        float F = 0.0f, Lv = 0.0f;
#pragma unroll
        for (int w = 0; w < 8; w++) {
            F += swF[w];
            Lv += swL[w];
        }
        g_pf[blockIdx.x] = F;
        g_pl[blockIdx.x] = Lv;
        __threadfence();
        unsigned old = atomicAdd(&g_done, 1u);
        slast = (old == NB - 1) ? 1 : 0;
    }
    __syncthreads();

    // --- last block: fold final scalar ---
    if (slast) {
        __threadfence();
        double* sFd = sred;
        double* sLd = sred + 256;
        double f = 0.0, l = 0.0;
        for (int k = tid; k < NB; k += 256) {
            f += (double)g_pf[k];
            l += (double)g_pl[k];
        }
        sFd[tid] = f;
        sLd[tid] = l;
        __syncthreads();
#pragma unroll
        for (int s = 128; s > 0; s >>= 1) {
            if (tid < s) {
                sFd[tid] += sFd[tid + s];
                sLd[tid] += sLd[tid + s];
            }
            __syncthreads();
        }
        if (tid == 0) {
            double n = (double)NTOT;
            double denom = sFd[0] / n + 0.01;
            out[0] = (float)(2.0 * (sLd[0] / n) / denom);
            g_done = 0;  // reset for next graph replay
        }
    }
}

extern "C" void kernel_launch(void* const* d_in, const int* in_sizes, int n_in,
                              void* d_out, int out_size) {
    const float* inp = (const float*)d_in[0];
    const float* tgt = (const float*)d_in[1];
    float* out = (float*)d_out;

    k1_f2<<<(NROWS * 32) / 256, 256>>>(tgt);
    k2_main<<<NB, 256>>>(inp, out);
}